// round 9
// baseline (speedup 1.0000x reference)
#include <cuda_runtime.h>
#include <cuda_fp16.h>
#include <cstdint>

// Chunked chain for L2 locality: process 32768 tokens in 4 chunks of 8192.
// Per chunk (serialized on stream): resid_ln -> gemm1 -> gemm2. The consumer
// of each scratch reads it while L2-resident; g_H/g_hd are chunk-sized rings
// so their writebacks mostly never reach DRAM.
// 1) convert_w: Wd,Wu -> half scratch (vectorized)
// 2) resid_ln : out = x + res^T (shortcut, fp32); H = half(LN(out)) -> ring
// 3) gemm1    : hd = half(relu(H @ Wd^T + bd)) -> ring  (cp.async 2-stage, LDSM)
// 4) gemm2    : out += hd @ Wu^T + bup  (LDSM, shortcut prefetch from L2)

#define NTOK 32768
#define DDIM 1024
#define BN   128
#define CHUNK 8192

__device__ __align__(16) __half g_H [(size_t)CHUNK * DDIM];  // ring (16MB)
__device__ __align__(16) __half g_hd[(size_t)CHUNK * BN];    // ring (2MB)
__device__ __align__(16) __half g_Wd[BN * DDIM];
__device__ __align__(16) __half g_Wu[DDIM * BN];

__device__ __forceinline__ void mma16(float* c, const uint32_t* a, const uint32_t* b) {
    asm volatile(
        "mma.sync.aligned.m16n8k16.row.col.f32.f16.f16.f32 "
        "{%0,%1,%2,%3}, {%4,%5,%6,%7}, {%8,%9}, {%0,%1,%2,%3};\n"
        : "+f"(c[0]), "+f"(c[1]), "+f"(c[2]), "+f"(c[3])
        : "r"(a[0]), "r"(a[1]), "r"(a[2]), "r"(a[3]), "r"(b[0]), "r"(b[1]));
}

__device__ __forceinline__ void ldsm4(uint32_t* r, const __half* p) {
    uint32_t a = (uint32_t)__cvta_generic_to_shared(p);
    asm volatile("ldmatrix.sync.aligned.m8n8.x4.shared.b16 {%0,%1,%2,%3}, [%4];\n"
                 : "=r"(r[0]), "=r"(r[1]), "=r"(r[2]), "=r"(r[3]) : "r"(a));
}

__device__ __forceinline__ void cp16(void* dst_sm, const void* src) {
    uint32_t a = (uint32_t)__cvta_generic_to_shared(dst_sm);
    asm volatile("cp.async.cg.shared.global [%0], [%1], 16;\n" :: "r"(a), "l"(src));
}
__device__ __forceinline__ void cp_commit() {
    asm volatile("cp.async.commit_group;\n");
}
template <int N>
__device__ __forceinline__ void cp_wait() {
    asm volatile("cp.async.wait_group %0;\n" :: "n"(N));
}

// ------------------------------------------------------------------ kernel 1
__global__ void convert_w(const float* __restrict__ Wd, const float* __restrict__ Wu) {
    const int i = (blockIdx.x * 256 + threadIdx.x) * 4; // 128 blocks
    const float4 a = *(const float4*)(Wd + i);
    const float4 b = *(const float4*)(Wu + i);
    __half2 a0 = __floats2half2_rn(a.x, a.y), a1 = __floats2half2_rn(a.z, a.w);
    __half2 b0 = __floats2half2_rn(b.x, b.y), b1 = __floats2half2_rn(b.z, b.w);
    uint2 ua, ub;
    ua.x = *(uint32_t*)&a0; ua.y = *(uint32_t*)&a1;
    ub.x = *(uint32_t*)&b0; ub.y = *(uint32_t*)&b1;
    *(uint2*)(g_Wd + i) = ua;
    *(uint2*)(g_Wu + i) = ub;
}

// ------------------------------------------------------------------ kernel 2
__global__ __launch_bounds__(256) void resid_ln(
    const float* __restrict__ x, const float* __restrict__ res,
    const float* __restrict__ gamma, const float* __restrict__ beta,
    float* __restrict__ out, int t_base)
{
    const int warp = threadIdx.x >> 5, lane = threadIdx.x & 31;
    const int nl = blockIdx.x * 8 + warp;          // local token (0..CHUNK)
    const int n  = t_base + nl;                    // global token
    const int s = n >> 3, b = n & 7;
    const float4* xr = (const float4*)(x + (size_t)n * DDIM);
    const float4* rr = (const float4*)(res + ((size_t)b * 4096 + s) * DDIM);
    float4* orow = (float4*)(out + (size_t)n * DDIM);
    uint2*  hrow = (uint2*)(g_H + (size_t)nl * DDIM);
    const float4* g4 = (const float4*)gamma;
    const float4* b4 = (const float4*)beta;

    float4 v[8];
    float sum = 0.f, sq = 0.f;
    #pragma unroll
    for (int i = 0; i < 8; ++i) {
        const int k = i * 32 + lane;
        const float4 a = xr[k], r = rr[k];
        float4 t;
        t.x = a.x + r.x; t.y = a.y + r.y; t.z = a.z + r.z; t.w = a.w + r.w;
        v[i] = t;
        orow[k] = t;
        sum += t.x + t.y + t.z + t.w;
        sq  += t.x * t.x + t.y * t.y + t.z * t.z + t.w * t.w;
    }
    #pragma unroll
    for (int o = 16; o > 0; o >>= 1) {
        sum += __shfl_xor_sync(0xffffffffu, sum, o);
        sq  += __shfl_xor_sync(0xffffffffu, sq, o);
    }
    const float mu   = sum * (1.f / 1024.f);
    const float var  = sq * (1.f / 1024.f) - mu * mu;
    const float rstd = rsqrtf(var + 1e-5f);

    #pragma unroll
    for (int i = 0; i < 8; ++i) {
        const int k = i * 32 + lane;
        const float4 g = g4[k], be = b4[k];
        __half2 h0 = __floats2half2_rn((v[i].x - mu) * rstd * g.x + be.x,
                                       (v[i].y - mu) * rstd * g.y + be.y);
        __half2 h1 = __floats2half2_rn((v[i].z - mu) * rstd * g.z + be.z,
                                       (v[i].w - mu) * rstd * g.w + be.w);
        uint2 u;
        u.x = *(uint32_t*)&h0;
        u.y = *(uint32_t*)&h1;
        hrow[k] = u;
    }
}

// ------------------------------------------------------------------ kernel 3
// CTA: 64 tokens x 128(BN). K chunks of 64 halves, 2-stage cp.async pipeline.
static constexpr int G1_AST  = 72;                     // row stride (halves)
static constexpr int G1_STG  = (64 + 128) * G1_AST;    // halves per stage
static constexpr int G1_SMEM = 2 * G1_STG * 2;         // 55296 B

__global__ __launch_bounds__(256, 3) void gemm1(const float* __restrict__ bd)
{
    extern __shared__ __half smB[];
    const int tid  = threadIdx.x;
    const int lane = tid & 31, warp = tid >> 5;
    const int l0   = blockIdx.x * 64;              // local token base (ring idx)

    const int mw = warp >> 2, nw = warp & 3;
    const int gid = lane >> 2, tig = lane & 3;

    const int a_row = (lane & 7) + ((lane >> 3) & 1) * 8;
    const int a_kof = (lane >> 4) * 8;
    const int b_row = (lane & 7) + (lane >> 4) * 8;
    const int b_kof = ((lane >> 3) & 1) * 8;

    auto issue = [&](int st, int kc) {
        __half* s = smB + st * G1_STG;
        const int kg0 = kc * 64;
        #pragma unroll
        for (int p = 0; p < 2; ++p) {           // A: 64 x 64 halves
            const int idx = p * 256 + tid;
            const int row = idx >> 3, j = (idx & 7) * 8;
            cp16(s + row * G1_AST + j, g_H + (size_t)(l0 + row) * DDIM + kg0 + j);
        }
        #pragma unroll
        for (int p = 0; p < 4; ++p) {           // B: 128 x 64 halves
            const int idx = p * 256 + tid;
            const int nn = idx >> 3, j = (idx & 7) * 8;
            cp16(s + 64 * G1_AST + nn * G1_AST + j, g_Wd + (size_t)nn * DDIM + kg0 + j);
        }
        cp_commit();
    };

    float acc[2][4][4];
    #pragma unroll
    for (int i = 0; i < 2; ++i)
        #pragma unroll
        for (int j = 0; j < 4; ++j)
            #pragma unroll
            for (int q = 0; q < 4; ++q) acc[i][j][q] = 0.f;

    issue(0, 0);
    issue(1, 1);

    #pragma unroll 1
    for (int kc = 0; kc < 16; ++kc) {
        if (kc == 15) cp_wait<0>(); else cp_wait<1>();
        __syncthreads();
        const __half* sa = smB + (kc & 1) * G1_STG;
        const __half* sb = sa + 64 * G1_AST;
        #pragma unroll
        for (int ks = 0; ks < 4; ++ks) {        // 4 x k16 = 64
            const int kb0 = ks * 16;
            uint32_t a[2][4], bf[2][4];
            #pragma unroll
            for (int mt = 0; mt < 2; ++mt)
                ldsm4(a[mt], sa + (mw * 32 + mt * 16 + a_row) * G1_AST + kb0 + a_kof);
            #pragma unroll
            for (int nt2 = 0; nt2 < 2; ++nt2)
                ldsm4(bf[nt2], sb + (nw * 32 + nt2 * 16 + b_row) * G1_AST + kb0 + b_kof);
            #pragma unroll
            for (int mt = 0; mt < 2; ++mt)
                #pragma unroll
                for (int nt = 0; nt < 4; ++nt)
                    mma16(acc[mt][nt], a[mt], bf[nt >> 1] + (nt & 1) * 2);
        }
        __syncthreads();
        if (kc + 2 < 16) issue((kc + 2) & 1, kc + 2);
    }

    // epilogue: +bd, relu, half -> g_hd (ring)
    #pragma unroll
    for (int mt = 0; mt < 2; ++mt) {
        #pragma unroll
        for (int nt = 0; nt < 4; ++nt) {
            const int row = mw * 32 + mt * 16 + gid;
            const int col = nw * 32 + nt * 8 + 2 * tig;
            const float b0 = bd[col], b1 = bd[col + 1];
            const float* c = acc[mt][nt];
            const size_t o = (size_t)(l0 + row) * BN + col;
            __half2 h0 = __floats2half2_rn(fmaxf(c[0] + b0, 0.f), fmaxf(c[1] + b1, 0.f));
            __half2 h1 = __floats2half2_rn(fmaxf(c[2] + b0, 0.f), fmaxf(c[3] + b1, 0.f));
            *(uint32_t*)(g_hd + o)          = *(uint32_t*)&h0;
            *(uint32_t*)(g_hd + o + 8 * BN) = *(uint32_t*)&h1;
        }
    }
}

// ------------------------------------------------------------------ kernel 4
// CTA: 64 tokens x 128 out-cols. Grid (8, CHUNK/64). Shortcut read is L2-hot
// (resid_ln for this chunk just wrote it).
static constexpr int G2_ST    = 136;
static constexpr int G2_A     = 64 * G2_ST;
static constexpr int G2_HB    = (64 + 128) * G2_ST;    // halves
static constexpr int G2_OUT   = 64 * 132;              // floats
static constexpr int G2_SMEM  = G2_HB * 2 + (G2_OUT + 128) * 4; // 86528 B

__global__ __launch_bounds__(256, 2) void gemm2(
    const float* __restrict__ bup, float* __restrict__ out, int t_base)
{
    extern __shared__ __half smC[];
    __half* shd = smC;
    __half* swu = smC + G2_A;
    float*  sout = (float*)(smC + G2_HB);
    float*  sbup = sout + G2_OUT;
    const int tid  = threadIdx.x;
    const int lane = tid & 31, warp = tid >> 5;
    const int nc = blockIdx.x;                 // col chunk (fastest)
    const int l0 = blockIdx.y * 64;            // local token tile
    const int t0 = t_base + l0;                // global token tile

    const int mw = warp >> 2, nw = warp & 3;
    const int gid = lane >> 2, tig = lane & 3;

    const int a_row = (lane & 7) + ((lane >> 3) & 1) * 8;
    const int a_kof = (lane >> 4) * 8;
    const int b_row = (lane & 7) + (lane >> 4) * 8;
    const int b_kof = ((lane >> 3) & 1) * 8;

    #pragma unroll
    for (int hk = 0; hk < 2; ++hk) {
        const int k0 = hk * 64;
        #pragma unroll
        for (int p = 0; p < 2; ++p) {           // hd: 64 x 64 halves (ring)
            const int idx = p * 256 + tid;
            const int row = idx >> 3, j = (idx & 7) * 8;
            cp16(shd + row * G2_ST + k0 + j, g_hd + (size_t)(l0 + row) * BN + k0 + j);
        }
        #pragma unroll
        for (int p = 0; p < 4; ++p) {           // Wu: 128 x 64 halves
            const int idx = p * 256 + tid;
            const int nn = idx >> 3, j = (idx & 7) * 8;
            cp16(swu + nn * G2_ST + k0 + j,
                 g_Wu + (size_t)(nc * 128 + nn) * BN + k0 + j);
        }
        cp_commit();
    }
    #pragma unroll
    for (int p = 0; p < 8; ++p) {               // shortcut: 64 x 128 floats
        const int idx = p * 256 + tid;
        const int row = idx >> 5, j = (idx & 31) * 4;
        cp16(sout + row * 132 + j, out + (size_t)(t0 + row) * DDIM + nc * 128 + j);
    }
    if (tid < 32) cp16(sbup + tid * 4, bup + nc * 128 + tid * 4);
    cp_commit();

    float acc[2][4][4];
    #pragma unroll
    for (int i = 0; i < 2; ++i)
        #pragma unroll
        for (int j = 0; j < 4; ++j)
            #pragma unroll
            for (int q = 0; q < 4; ++q) acc[i][j][q] = 0.f;

    #pragma unroll
    for (int hk = 0; hk < 2; ++hk) {
        if (hk == 0) cp_wait<2>(); else cp_wait<1>();
        __syncthreads();
        #pragma unroll
        for (int ks = 0; ks < 4; ++ks) {
            const int kb0 = hk * 64 + ks * 16;
            uint32_t a[2][4], bf[2][4];
            #pragma unroll
            for (int mt = 0; mt < 2; ++mt)
                ldsm4(a[mt], shd + (mw * 32 + mt * 16 + a_row) * G2_ST + kb0 + a_kof);
            #pragma unroll
            for (int nt2 = 0; nt2 < 2; ++nt2)
                ldsm4(bf[nt2], swu + (nw * 32 + nt2 * 16 + b_row) * G2_ST + kb0 + b_kof);
            #pragma unroll
            for (int mt = 0; mt < 2; ++mt)
                #pragma unroll
                for (int nt = 0; nt < 4; ++nt)
                    mma16(acc[mt][nt], a[mt], bf[nt >> 1] + (nt & 1) * 2);
        }
    }

    cp_wait<0>();
    __syncthreads();

    #pragma unroll
    for (int mt = 0; mt < 2; ++mt) {
        #pragma unroll
        for (int nt = 0; nt < 4; ++nt) {
            const int row  = mw * 32 + mt * 16 + gid;
            const int col  = nw * 32 + nt * 8 + 2 * tig;
            const int gcol = nc * 128 + col;
            const float b0 = sbup[col], b1 = sbup[col + 1];
            const size_t off  = (size_t)(t0 + row) * DDIM + gcol;
            const size_t off2 = off + (size_t)8 * DDIM;
            const float* c = acc[mt][nt];
            const float2 s0 = *(const float2*)(sout + row * 132 + col);
            const float2 s1 = *(const float2*)(sout + (row + 8) * 132 + col);
            float2 o0, o1;
            o0.x = c[0] + b0 + s0.x; o0.y = c[1] + b1 + s0.y;
            o1.x = c[2] + b0 + s1.x; o1.y = c[3] + b1 + s1.y;
            *(float2*)(out + off)  = o0;
            *(float2*)(out + off2) = o1;
        }
    }
}

// ------------------------------------------------------------------ launch
extern "C" void kernel_launch(void* const* d_in, const int* in_sizes, int n_in,
                              void* d_out, int out_size) {
    const float* x     = (const float*)d_in[0];
    const float* res   = (const float*)d_in[1];
    const float* gamma = (const float*)d_in[2];
    const float* beta  = (const float*)d_in[3];
    const float* Wd    = (const float*)d_in[4];
    const float* bd    = (const float*)d_in[5];
    const float* Wu    = (const float*)d_in[6];
    const float* bup   = (const float*)d_in[7];
    float* out = (float*)d_out;

    static bool attr_done = false;
    if (!attr_done) {
        cudaFuncSetAttribute(gemm1, cudaFuncAttributeMaxDynamicSharedMemorySize, G1_SMEM);
        cudaFuncSetAttribute(gemm2, cudaFuncAttributeMaxDynamicSharedMemorySize, G2_SMEM);
        attr_done = true;
    }

    convert_w<<<128, 256>>>(Wd, Wu);
    for (int c = 0; c < NTOK / CHUNK; ++c) {
        const int t_base = c * CHUNK;
        resid_ln<<<CHUNK / 8, 256>>>(x, res, gamma, beta, out, t_base);
        gemm1<<<CHUNK / 64, 256, G1_SMEM>>>(bd);
        gemm2<<<dim3(8, CHUNK / 64), 256, G2_SMEM>>>(bup, out, t_base);
    }
}

// round 10
// speedup vs baseline: 1.3653x; 1.3653x over previous
#include <cuda_runtime.h>
#include <cuda_fp16.h>
#include <cstdint>

// LN folded into GEMM1; shortcut stored as half.
// 1) convert_w: g_Wd = half(gamma ⊙ Wd), g_Wu = half(Wu)
// 2) prep_s   : s1 = Wd@gamma, s2 = Wd@beta + bd  (fp32, 128 each)
// 3) resid_ln : v = x+res^T -> g_sc (half); mu,rstd -> g_mu,g_rs. NO fp32 write.
// 4) gemm1    : acc = v @ g_Wd^T;  hd = relu(rstd*(acc - mu*s1) + s2) -> g_hd
// 5) gemm2    : out = float(g_sc) + bup + hd @ g_Wu^T   (only fp32 traffic)

#define NTOK 32768
#define DDIM 1024
#define BN   128

__device__ __align__(16) __half g_sc[(size_t)NTOK * DDIM];   // 64MB
__device__ __align__(16) __half g_hd[(size_t)NTOK * BN];     // 8MB
__device__ __align__(16) __half g_Wd[BN * DDIM];
__device__ __align__(16) __half g_Wu[DDIM * BN];
__device__ float g_mu[NTOK];
__device__ float g_rs[NTOK];
__device__ float g_s1[BN];
__device__ float g_s2[BN];

__device__ __forceinline__ void mma16(float* c, const uint32_t* a, const uint32_t* b) {
    asm volatile(
        "mma.sync.aligned.m16n8k16.row.col.f32.f16.f16.f32 "
        "{%0,%1,%2,%3}, {%4,%5,%6,%7}, {%8,%9}, {%0,%1,%2,%3};\n"
        : "+f"(c[0]), "+f"(c[1]), "+f"(c[2]), "+f"(c[3])
        : "r"(a[0]), "r"(a[1]), "r"(a[2]), "r"(a[3]), "r"(b[0]), "r"(b[1]));
}

__device__ __forceinline__ void ldsm4(uint32_t* r, const __half* p) {
    uint32_t a = (uint32_t)__cvta_generic_to_shared(p);
    asm volatile("ldmatrix.sync.aligned.m8n8.x4.shared.b16 {%0,%1,%2,%3}, [%4];\n"
                 : "=r"(r[0]), "=r"(r[1]), "=r"(r[2]), "=r"(r[3]) : "r"(a));
}

__device__ __forceinline__ void cp16(void* dst_sm, const void* src) {
    uint32_t a = (uint32_t)__cvta_generic_to_shared(dst_sm);
    asm volatile("cp.async.cg.shared.global [%0], [%1], 16;\n" :: "r"(a), "l"(src));
}
__device__ __forceinline__ void cp_commit() {
    asm volatile("cp.async.commit_group;\n");
}
template <int N>
__device__ __forceinline__ void cp_wait() {
    asm volatile("cp.async.wait_group %0;\n" :: "n"(N));
}

// ------------------------------------------------------------------ kernel 1
__global__ void convert_w(const float* __restrict__ Wd, const float* __restrict__ Wu,
                          const float* __restrict__ gamma) {
    const int i = (blockIdx.x * 256 + threadIdx.x) * 4; // 128 blocks
    float4 a = *(const float4*)(Wd + i);
    const int k = i & 1023;                             // col within Wd row
    const float4 g = *(const float4*)(gamma + k);
    a.x *= g.x; a.y *= g.y; a.z *= g.z; a.w *= g.w;
    const float4 b = *(const float4*)(Wu + i);
    __half2 a0 = __floats2half2_rn(a.x, a.y), a1 = __floats2half2_rn(a.z, a.w);
    __half2 b0 = __floats2half2_rn(b.x, b.y), b1 = __floats2half2_rn(b.z, b.w);
    uint2 ua, ub;
    ua.x = *(uint32_t*)&a0; ua.y = *(uint32_t*)&a1;
    ub.x = *(uint32_t*)&b0; ub.y = *(uint32_t*)&b1;
    *(uint2*)(g_Wd + i) = ua;
    *(uint2*)(g_Wu + i) = ub;
}

// ------------------------------------------------------------------ kernel 2
__global__ __launch_bounds__(256) void prep_s(
    const float* __restrict__ Wd, const float* __restrict__ gamma,
    const float* __restrict__ beta, const float* __restrict__ bd)
{
    __shared__ float r1[256], r2[256];
    const int j = blockIdx.x;                   // 128 blocks
    const int tid = threadIdx.x;
    const float* wr = Wd + (size_t)j * DDIM;
    float s1 = 0.f, s2 = 0.f;
    for (int k = tid; k < DDIM; k += 256) {
        const float w = wr[k];
        s1 += gamma[k] * w;
        s2 += beta[k] * w;
    }
    r1[tid] = s1; r2[tid] = s2;
    __syncthreads();
    for (int o = 128; o > 0; o >>= 1) {
        if (tid < o) { r1[tid] += r1[tid + o]; r2[tid] += r2[tid + o]; }
        __syncthreads();
    }
    if (tid == 0) { g_s1[j] = r1[0]; g_s2[j] = r2[0] + bd[j]; }
}

// ------------------------------------------------------------------ kernel 3
__global__ __launch_bounds__(256) void resid_ln(
    const float* __restrict__ x, const float* __restrict__ res)
{
    const int warp = threadIdx.x >> 5, lane = threadIdx.x & 31;
    const int n = blockIdx.x * 8 + warp;           // 4096 blocks
    const int s = n >> 3, b = n & 7;
    const float4* xr = (const float4*)(x + (size_t)n * DDIM);
    const float4* rr = (const float4*)(res + ((size_t)b * 4096 + s) * DDIM);
    uint2* hrow = (uint2*)(g_sc + (size_t)n * DDIM);

    float sum = 0.f, sq = 0.f;
    #pragma unroll
    for (int i = 0; i < 8; ++i) {
        const int k = i * 32 + lane;
        const float4 a = xr[k], r = rr[k];
        float4 t;
        t.x = a.x + r.x; t.y = a.y + r.y; t.z = a.z + r.z; t.w = a.w + r.w;
        sum += t.x + t.y + t.z + t.w;
        sq  += t.x * t.x + t.y * t.y + t.z * t.z + t.w * t.w;
        __half2 h0 = __floats2half2_rn(t.x, t.y);
        __half2 h1 = __floats2half2_rn(t.z, t.w);
        uint2 u;
        u.x = *(uint32_t*)&h0;
        u.y = *(uint32_t*)&h1;
        hrow[k] = u;
    }
    #pragma unroll
    for (int o = 16; o > 0; o >>= 1) {
        sum += __shfl_xor_sync(0xffffffffu, sum, o);
        sq  += __shfl_xor_sync(0xffffffffu, sq, o);
    }
    if (lane == 0) {
        const float mu  = sum * (1.f / 1024.f);
        const float var = sq * (1.f / 1024.f) - mu * mu;
        g_mu[n] = mu;
        g_rs[n] = rsqrtf(var + 1e-5f);
    }
}

// ------------------------------------------------------------------ kernel 4
// CTA: 64 tokens x 128(BN). K chunks of 64 halves, 2-stage cp.async pipeline.
// smem: stats/consts 1536B, then 2 stages of {A 64x72, B 128x72} halves.
static constexpr int OFF1_MU  = 0;
static constexpr int OFF1_RS  = 256;
static constexpr int OFF1_S1  = 512;
static constexpr int OFF1_S2  = 1024;
static constexpr int OFF1_T   = 1536;
static constexpr int G1_AST   = 72;
static constexpr int G1_STG   = (64 + 128) * G1_AST;     // halves
static constexpr int G1_SMEM  = OFF1_T + 2 * G1_STG * 2; // 56832 B

__global__ __launch_bounds__(256, 3) void gemm1()
{
    extern __shared__ char smem1[];
    float*  smu = (float*)(smem1 + OFF1_MU);
    float*  srs = (float*)(smem1 + OFF1_RS);
    float*  ss1 = (float*)(smem1 + OFF1_S1);
    float*  ss2 = (float*)(smem1 + OFF1_S2);
    __half* smB = (__half*)(smem1 + OFF1_T);
    const int tid  = threadIdx.x;
    const int lane = tid & 31, warp = tid >> 5;
    const int t0   = blockIdx.x * 64;

    const int mw = warp >> 2, nw = warp & 3;
    const int gid = lane >> 2, tig = lane & 3;
    const int a_row = (lane & 7) + ((lane >> 3) & 1) * 8;
    const int a_kof = (lane >> 4) * 8;
    const int b_row = (lane & 7) + (lane >> 4) * 8;
    const int b_kof = ((lane >> 3) & 1) * 8;

    if (tid < 64)  { smu[tid] = g_mu[t0 + tid]; srs[tid] = g_rs[t0 + tid]; }
    else if (tid < 192) {
        const int j = tid - 64;
        ss1[j] = g_s1[j];
        ss2[j] = g_s2[j];
    }

    auto issue = [&](int st, int kc) {
        __half* s = smB + st * G1_STG;
        const int kg0 = kc * 64;
        #pragma unroll
        for (int p = 0; p < 2; ++p) {           // A: 64 x 64 halves from g_sc
            const int idx = p * 256 + tid;
            const int row = idx >> 3, j = (idx & 7) * 8;
            cp16(s + row * G1_AST + j, g_sc + (size_t)(t0 + row) * DDIM + kg0 + j);
        }
        #pragma unroll
        for (int p = 0; p < 4; ++p) {           // B: 128 x 64 halves
            const int idx = p * 256 + tid;
            const int nn = idx >> 3, j = (idx & 7) * 8;
            cp16(s + 64 * G1_AST + nn * G1_AST + j, g_Wd + (size_t)nn * DDIM + kg0 + j);
        }
        cp_commit();
    };

    float acc[2][4][4];
    #pragma unroll
    for (int i = 0; i < 2; ++i)
        #pragma unroll
        for (int j = 0; j < 4; ++j)
            #pragma unroll
            for (int q = 0; q < 4; ++q) acc[i][j][q] = 0.f;

    issue(0, 0);
    issue(1, 1);

    #pragma unroll 1
    for (int kc = 0; kc < 16; ++kc) {
        if (kc == 15) cp_wait<0>(); else cp_wait<1>();
        __syncthreads();
        const __half* sa = smB + (kc & 1) * G1_STG;
        const __half* sb = sa + 64 * G1_AST;
        #pragma unroll
        for (int ks = 0; ks < 4; ++ks) {
            const int kb0 = ks * 16;
            uint32_t a[2][4], bf[2][4];
            #pragma unroll
            for (int mt = 0; mt < 2; ++mt)
                ldsm4(a[mt], sa + (mw * 32 + mt * 16 + a_row) * G1_AST + kb0 + a_kof);
            #pragma unroll
            for (int nt2 = 0; nt2 < 2; ++nt2)
                ldsm4(bf[nt2], sb + (nw * 32 + nt2 * 16 + b_row) * G1_AST + kb0 + b_kof);
            #pragma unroll
            for (int mt = 0; mt < 2; ++mt)
                #pragma unroll
                for (int nt = 0; nt < 4; ++nt)
                    mma16(acc[mt][nt], a[mt], bf[nt >> 1] + (nt & 1) * 2);
        }
        __syncthreads();
        if (kc + 2 < 16) issue((kc + 2) & 1, kc + 2);
    }

    // epilogue: hd = relu(rstd*(acc - mu*s1) + s2) -> g_hd
    #pragma unroll
    for (int mt = 0; mt < 2; ++mt) {
        #pragma unroll
        for (int nt = 0; nt < 4; ++nt) {
            const int row = mw * 32 + mt * 16 + gid;
            const int col = nw * 32 + nt * 8 + 2 * tig;
            const float mu0 = smu[row],     rs0 = srs[row];
            const float mu1 = smu[row + 8], rs1 = srs[row + 8];
            const float s10 = ss1[col], s11 = ss1[col + 1];
            const float s20 = ss2[col], s21 = ss2[col + 1];
            const float* c = acc[mt][nt];
            const size_t o = (size_t)(t0 + row) * BN + col;
            __half2 h0 = __floats2half2_rn(
                fmaxf(rs0 * (c[0] - mu0 * s10) + s20, 0.f),
                fmaxf(rs0 * (c[1] - mu0 * s11) + s21, 0.f));
            __half2 h1 = __floats2half2_rn(
                fmaxf(rs1 * (c[2] - mu1 * s10) + s20, 0.f),
                fmaxf(rs1 * (c[3] - mu1 * s11) + s21, 0.f));
            *(uint32_t*)(g_hd + o)          = *(uint32_t*)&h0;
            *(uint32_t*)(g_hd + o + 8 * BN) = *(uint32_t*)&h1;
        }
    }
}

// ------------------------------------------------------------------ kernel 5
// CTA: 64 tokens x 128 out-cols. Grid (8, 512). Shortcut from g_sc (half).
static constexpr int G2_ST    = 136;                   // halves
static constexpr int G2_HD    = 0;                     // shd 64x136
static constexpr int G2_WU    = 64 * G2_ST;            // swu 128x136
static constexpr int G2_SC    = G2_WU + 128 * G2_ST;   // ssc 64x136
static constexpr int G2_END   = G2_SC + 64 * G2_ST;    // halves
static constexpr int G2_SMEM  = G2_END * 2 + 128 * 4;  // 70144 B

__global__ __launch_bounds__(256, 3) void gemm2(
    const float* __restrict__ bup, float* __restrict__ out)
{
    extern __shared__ __half smC[];
    __half* shd = smC + G2_HD;
    __half* swu = smC + G2_WU;
    __half* ssc = smC + G2_SC;
    float*  sbup = (float*)(smC + G2_END);
    const int tid  = threadIdx.x;
    const int lane = tid & 31, warp = tid >> 5;
    const int nc = blockIdx.x;                 // col chunk (fastest)
    const int t0 = blockIdx.y * 64;            // token tile

    const int mw = warp >> 2, nw = warp & 3;
    const int gid = lane >> 2, tig = lane & 3;

    const int a_row = (lane & 7) + ((lane >> 3) & 1) * 8;
    const int a_kof = (lane >> 4) * 8;
    const int b_row = (lane & 7) + (lane >> 4) * 8;
    const int b_kof = ((lane >> 3) & 1) * 8;

    #pragma unroll
    for (int hk = 0; hk < 2; ++hk) {
        const int k0 = hk * 64;
        #pragma unroll
        for (int p = 0; p < 2; ++p) {           // hd: 64 x 64 halves
            const int idx = p * 256 + tid;
            const int row = idx >> 3, j = (idx & 7) * 8;
            cp16(shd + row * G2_ST + k0 + j, g_hd + (size_t)(t0 + row) * BN + k0 + j);
        }
        #pragma unroll
        for (int p = 0; p < 4; ++p) {           // Wu: 128 x 64 halves
            const int idx = p * 256 + tid;
            const int nn = idx >> 3, j = (idx & 7) * 8;
            cp16(swu + nn * G2_ST + k0 + j,
                 g_Wu + (size_t)(nc * 128 + nn) * BN + k0 + j);
        }
        cp_commit();
    }
    #pragma unroll
    for (int p = 0; p < 4; ++p) {               // shortcut: 64 x 128 halves
        const int idx = p * 256 + tid;
        const int row = idx >> 4, j = (idx & 15) * 8;
        cp16(ssc + row * G2_ST + j,
             g_sc + (size_t)(t0 + row) * DDIM + nc * 128 + j);
    }
    if (tid < 32) cp16(sbup + tid * 4, bup + nc * 128 + tid * 4);
    cp_commit();

    float acc[2][4][4];
    #pragma unroll
    for (int i = 0; i < 2; ++i)
        #pragma unroll
        for (int j = 0; j < 4; ++j)
            #pragma unroll
            for (int q = 0; q < 4; ++q) acc[i][j][q] = 0.f;

    #pragma unroll
    for (int hk = 0; hk < 2; ++hk) {
        if (hk == 0) cp_wait<2>(); else cp_wait<1>();
        __syncthreads();
        #pragma unroll
        for (int ks = 0; ks < 4; ++ks) {
            const int kb0 = hk * 64 + ks * 16;
            uint32_t a[2][4], bf[2][4];
            #pragma unroll
            for (int mt = 0; mt < 2; ++mt)
                ldsm4(a[mt], shd + (mw * 32 + mt * 16 + a_row) * G2_ST + kb0 + a_kof);
            #pragma unroll
            for (int nt2 = 0; nt2 < 2; ++nt2)
                ldsm4(bf[nt2], swu + (nw * 32 + nt2 * 16 + b_row) * G2_ST + kb0 + b_kof);
            #pragma unroll
            for (int mt = 0; mt < 2; ++mt)
                #pragma unroll
                for (int nt = 0; nt < 4; ++nt)
                    mma16(acc[mt][nt], a[mt], bf[nt >> 1] + (nt & 1) * 2);
        }
    }

    cp_wait<0>();
    __syncthreads();

    #pragma unroll
    for (int mt = 0; mt < 2; ++mt) {
        #pragma unroll
        for (int nt = 0; nt < 4; ++nt) {
            const int row  = mw * 32 + mt * 16 + gid;
            const int col  = nw * 32 + nt * 8 + 2 * tig;
            const int gcol = nc * 128 + col;
            const float b0 = sbup[col], b1 = sbup[col + 1];
            const size_t off  = (size_t)(t0 + row) * DDIM + gcol;
            const size_t off2 = off + (size_t)8 * DDIM;
            const float* c = acc[mt][nt];
            const float2 s0 = __half22float2(*(const __half2*)(ssc + row * G2_ST + col));
            const float2 s1 = __half22float2(*(const __half2*)(ssc + (row + 8) * G2_ST + col));
            float2 o0, o1;
            o0.x = c[0] + b0 + s0.x; o0.y = c[1] + b1 + s0.y;
            o1.x = c[2] + b0 + s1.x; o1.y = c[3] + b1 + s1.y;
            *(float2*)(out + off)  = o0;
            *(float2*)(out + off2) = o1;
        }
    }
}

// ------------------------------------------------------------------ launch
extern "C" void kernel_launch(void* const* d_in, const int* in_sizes, int n_in,
                              void* d_out, int out_size) {
    const float* x     = (const float*)d_in[0];
    const float* res   = (const float*)d_in[1];
    const float* gamma = (const float*)d_in[2];
    const float* beta  = (const float*)d_in[3];
    const float* Wd    = (const float*)d_in[4];
    const float* bd    = (const float*)d_in[5];
    const float* Wu    = (const float*)d_in[6];
    const float* bup   = (const float*)d_in[7];
    float* out = (float*)d_out;

    static bool attr_done = false;
    if (!attr_done) {
        cudaFuncSetAttribute(gemm1, cudaFuncAttributeMaxDynamicSharedMemorySize, G1_SMEM);
        cudaFuncSetAttribute(gemm2, cudaFuncAttributeMaxDynamicSharedMemorySize, G2_SMEM);
        attr_done = true;
    }

    convert_w<<<128, 256>>>(Wd, Wu, gamma);
    prep_s<<<128, 256>>>(Wd, gamma, beta, bd);
    resid_ln<<<4096, 256>>>(x, res);
    gemm1<<<512, 256, G1_SMEM>>>();
    gemm2<<<dim3(8, 512), 256, G2_SMEM>>>(bup, out);
}

// round 11
// speedup vs baseline: 1.3770x; 1.0086x over previous
#include <cuda_runtime.h>
#include <cuda_fp16.h>
#include <cstdint>

// LN folded into GEMM1; shortcut stored as half.
// 1) convert_w: g_Wd = half(gamma ⊙ Wd), g_Wu = half(Wu)
// 2) prep_s   : s1 = Wd@gamma, s2 = Wd@beta + bd  (fp32, 128 each)
// 3) resid_ln : v = x+res^T -> g_sc (half); mu,rstd -> g_mu,g_rs
// 4) gemm1    : acc = v @ g_Wd^T;  hd = relu(rstd*(acc - mu*s1) + s2) -> g_hd
//               (occ 4 single wave, single-sync pipeline, reversed tile order)
// 5) gemm2    : out = float(g_sc) + bup + hd @ g_Wu^T

#define NTOK 32768
#define DDIM 1024
#define BN   128

__device__ __align__(16) __half g_sc[(size_t)NTOK * DDIM];   // 64MB
__device__ __align__(16) __half g_hd[(size_t)NTOK * BN];     // 8MB
__device__ __align__(16) __half g_Wd[BN * DDIM];
__device__ __align__(16) __half g_Wu[DDIM * BN];
__device__ float g_mu[NTOK];
__device__ float g_rs[NTOK];
__device__ float g_s1[BN];
__device__ float g_s2[BN];

__device__ __forceinline__ void mma16(float* c, const uint32_t* a, const uint32_t* b) {
    asm volatile(
        "mma.sync.aligned.m16n8k16.row.col.f32.f16.f16.f32 "
        "{%0,%1,%2,%3}, {%4,%5,%6,%7}, {%8,%9}, {%0,%1,%2,%3};\n"
        : "+f"(c[0]), "+f"(c[1]), "+f"(c[2]), "+f"(c[3])
        : "r"(a[0]), "r"(a[1]), "r"(a[2]), "r"(a[3]), "r"(b[0]), "r"(b[1]));
}

__device__ __forceinline__ void ldsm4(uint32_t* r, const __half* p) {
    uint32_t a = (uint32_t)__cvta_generic_to_shared(p);
    asm volatile("ldmatrix.sync.aligned.m8n8.x4.shared.b16 {%0,%1,%2,%3}, [%4];\n"
                 : "=r"(r[0]), "=r"(r[1]), "=r"(r[2]), "=r"(r[3]) : "r"(a));
}

__device__ __forceinline__ void cp16(void* dst_sm, const void* src) {
    uint32_t a = (uint32_t)__cvta_generic_to_shared(dst_sm);
    asm volatile("cp.async.cg.shared.global [%0], [%1], 16;\n" :: "r"(a), "l"(src));
}
__device__ __forceinline__ void cp_commit() {
    asm volatile("cp.async.commit_group;\n");
}
template <int N>
__device__ __forceinline__ void cp_wait() {
    asm volatile("cp.async.wait_group %0;\n" :: "n"(N));
}

// ------------------------------------------------------------------ kernel 1
__global__ void convert_w(const float* __restrict__ Wd, const float* __restrict__ Wu,
                          const float* __restrict__ gamma) {
    const int i = (blockIdx.x * 256 + threadIdx.x) * 4; // 128 blocks
    float4 a = *(const float4*)(Wd + i);
    const int k = i & 1023;                             // col within Wd row
    const float4 g = *(const float4*)(gamma + k);
    a.x *= g.x; a.y *= g.y; a.z *= g.z; a.w *= g.w;
    const float4 b = *(const float4*)(Wu + i);
    __half2 a0 = __floats2half2_rn(a.x, a.y), a1 = __floats2half2_rn(a.z, a.w);
    __half2 b0 = __floats2half2_rn(b.x, b.y), b1 = __floats2half2_rn(b.z, b.w);
    uint2 ua, ub;
    ua.x = *(uint32_t*)&a0; ua.y = *(uint32_t*)&a1;
    ub.x = *(uint32_t*)&b0; ub.y = *(uint32_t*)&b1;
    *(uint2*)(g_Wd + i) = ua;
    *(uint2*)(g_Wu + i) = ub;
}

// ------------------------------------------------------------------ kernel 2
__global__ __launch_bounds__(256) void prep_s(
    const float* __restrict__ Wd, const float* __restrict__ gamma,
    const float* __restrict__ beta, const float* __restrict__ bd)
{
    __shared__ float r1[256], r2[256];
    const int j = blockIdx.x;                   // 128 blocks
    const int tid = threadIdx.x;
    const float* wr = Wd + (size_t)j * DDIM;
    float s1 = 0.f, s2 = 0.f;
    for (int k = tid; k < DDIM; k += 256) {
        const float w = wr[k];
        s1 += gamma[k] * w;
        s2 += beta[k] * w;
    }
    r1[tid] = s1; r2[tid] = s2;
    __syncthreads();
    for (int o = 128; o > 0; o >>= 1) {
        if (tid < o) { r1[tid] += r1[tid + o]; r2[tid] += r2[tid + o]; }
        __syncthreads();
    }
    if (tid == 0) { g_s1[j] = r1[0]; g_s2[j] = r2[0] + bd[j]; }
}

// ------------------------------------------------------------------ kernel 3
__global__ __launch_bounds__(256) void resid_ln(
    const float* __restrict__ x, const float* __restrict__ res)
{
    const int warp = threadIdx.x >> 5, lane = threadIdx.x & 31;
    const int n = blockIdx.x * 8 + warp;           // 4096 blocks
    const int s = n >> 3, b = n & 7;
    const float4* xr = (const float4*)(x + (size_t)n * DDIM);
    const float4* rr = (const float4*)(res + ((size_t)b * 4096 + s) * DDIM);
    uint2* hrow = (uint2*)(g_sc + (size_t)n * DDIM);

    float sum = 0.f, sq = 0.f;
    #pragma unroll
    for (int i = 0; i < 8; ++i) {
        const int k = i * 32 + lane;
        const float4 a = xr[k], r = rr[k];
        float4 t;
        t.x = a.x + r.x; t.y = a.y + r.y; t.z = a.z + r.z; t.w = a.w + r.w;
        sum += t.x + t.y + t.z + t.w;
        sq  += t.x * t.x + t.y * t.y + t.z * t.z + t.w * t.w;
        __half2 h0 = __floats2half2_rn(t.x, t.y);
        __half2 h1 = __floats2half2_rn(t.z, t.w);
        uint2 u;
        u.x = *(uint32_t*)&h0;
        u.y = *(uint32_t*)&h1;
        hrow[k] = u;
    }
    #pragma unroll
    for (int o = 16; o > 0; o >>= 1) {
        sum += __shfl_xor_sync(0xffffffffu, sum, o);
        sq  += __shfl_xor_sync(0xffffffffu, sq, o);
    }
    if (lane == 0) {
        const float mu  = sum * (1.f / 1024.f);
        const float var = sq * (1.f / 1024.f) - mu * mu;
        g_mu[n] = mu;
        g_rs[n] = rsqrtf(var + 1e-5f);
    }
}

// ------------------------------------------------------------------ kernel 4
// CTA: 64 tokens x 128(BN). K chunks of 64 halves, single-sync 2-stage.
// occ 4 (regs capped 64) -> 592 slots >= 512 CTAs: single wave.
static constexpr int OFF1_MU  = 0;
static constexpr int OFF1_RS  = 256;
static constexpr int OFF1_S1  = 512;
static constexpr int OFF1_S2  = 1024;
static constexpr int OFF1_T   = 1536;
static constexpr int G1_AST   = 72;
static constexpr int G1_STG   = (64 + 128) * G1_AST;     // halves
static constexpr int G1_SMEM  = OFF1_T + 2 * G1_STG * 2; // 56832 B

__global__ __launch_bounds__(256, 4) void gemm1()
{
    extern __shared__ char smem1[];
    float*  smu = (float*)(smem1 + OFF1_MU);
    float*  srs = (float*)(smem1 + OFF1_RS);
    float*  ss1 = (float*)(smem1 + OFF1_S1);
    float*  ss2 = (float*)(smem1 + OFF1_S2);
    __half* smB = (__half*)(smem1 + OFF1_T);
    const int tid  = threadIdx.x;
    const int lane = tid & 31, warp = tid >> 5;
    // reversed tile order: read the L2-resident tail of g_sc first
    const int t0   = (int)(gridDim.x - 1 - blockIdx.x) * 64;

    const int mw = warp >> 2, nw = warp & 3;
    const int gid = lane >> 2, tig = lane & 3;
    const int a_row = (lane & 7) + ((lane >> 3) & 1) * 8;
    const int a_kof = (lane >> 4) * 8;
    const int b_row = (lane & 7) + (lane >> 4) * 8;
    const int b_kof = ((lane >> 3) & 1) * 8;

    if (tid < 64)  { smu[tid] = g_mu[t0 + tid]; srs[tid] = g_rs[t0 + tid]; }
    else if (tid < 192) {
        const int j = tid - 64;
        ss1[j] = g_s1[j];
        ss2[j] = g_s2[j];
    }

    auto issue = [&](int st, int kc) {
        __half* s = smB + st * G1_STG;
        const int kg0 = kc * 64;
        #pragma unroll
        for (int p = 0; p < 2; ++p) {           // A: 64 x 64 halves from g_sc
            const int idx = p * 256 + tid;
            const int row = idx >> 3, j = (idx & 7) * 8;
            cp16(s + row * G1_AST + j, g_sc + (size_t)(t0 + row) * DDIM + kg0 + j);
        }
        #pragma unroll
        for (int p = 0; p < 4; ++p) {           // B: 128 x 64 halves
            const int idx = p * 256 + tid;
            const int nn = idx >> 3, j = (idx & 7) * 8;
            cp16(s + 64 * G1_AST + nn * G1_AST + j, g_Wd + (size_t)nn * DDIM + kg0 + j);
        }
        cp_commit();
    };

    float acc[2][4][4];
    #pragma unroll
    for (int i = 0; i < 2; ++i)
        #pragma unroll
        for (int j = 0; j < 4; ++j)
            #pragma unroll
            for (int q = 0; q < 4; ++q) acc[i][j][q] = 0.f;

    issue(0, 0);

    #pragma unroll 1
    for (int kc = 0; kc < 16; ++kc) {
        cp_wait<0>();
        __syncthreads();
        if (kc + 1 < 16) issue((kc + 1) & 1, kc + 1);   // overlaps this MMA chunk
        const __half* sa = smB + (kc & 1) * G1_STG;
        const __half* sb = sa + 64 * G1_AST;
        #pragma unroll
        for (int ks = 0; ks < 4; ++ks) {
            const int kb0 = ks * 16;
            uint32_t a[2][4], bf[2][4];
            #pragma unroll
            for (int mt = 0; mt < 2; ++mt)
                ldsm4(a[mt], sa + (mw * 32 + mt * 16 + a_row) * G1_AST + kb0 + a_kof);
            #pragma unroll
            for (int nt2 = 0; nt2 < 2; ++nt2)
                ldsm4(bf[nt2], sb + (nw * 32 + nt2 * 16 + b_row) * G1_AST + kb0 + b_kof);
            #pragma unroll
            for (int mt = 0; mt < 2; ++mt)
                #pragma unroll
                for (int nt = 0; nt < 4; ++nt)
                    mma16(acc[mt][nt], a[mt], bf[nt >> 1] + (nt & 1) * 2);
        }
    }

    // epilogue: hd = relu(rstd*(acc - mu*s1) + s2) -> g_hd
    #pragma unroll
    for (int mt = 0; mt < 2; ++mt) {
        #pragma unroll
        for (int nt = 0; nt < 4; ++nt) {
            const int row = mw * 32 + mt * 16 + gid;
            const int col = nw * 32 + nt * 8 + 2 * tig;
            const float mu0 = smu[row],     rs0 = srs[row];
            const float mu1 = smu[row + 8], rs1 = srs[row + 8];
            const float s10 = ss1[col], s11 = ss1[col + 1];
            const float s20 = ss2[col], s21 = ss2[col + 1];
            const float* c = acc[mt][nt];
            const size_t o = (size_t)(t0 + row) * BN + col;
            __half2 h0 = __floats2half2_rn(
                fmaxf(rs0 * (c[0] - mu0 * s10) + s20, 0.f),
                fmaxf(rs0 * (c[1] - mu0 * s11) + s21, 0.f));
            __half2 h1 = __floats2half2_rn(
                fmaxf(rs1 * (c[2] - mu1 * s10) + s20, 0.f),
                fmaxf(rs1 * (c[3] - mu1 * s11) + s21, 0.f));
            *(uint32_t*)(g_hd + o)          = *(uint32_t*)&h0;
            *(uint32_t*)(g_hd + o + 8 * BN) = *(uint32_t*)&h1;
        }
    }
}

// ------------------------------------------------------------------ kernel 5
// CTA: 64 tokens x 128 out-cols. Grid (8, 512). Shortcut from g_sc (half).
static constexpr int G2_ST    = 136;                   // halves
static constexpr int G2_HD    = 0;                     // shd 64x136
static constexpr int G2_WU    = 64 * G2_ST;            // swu 128x136
static constexpr int G2_SC    = G2_WU + 128 * G2_ST;   // ssc 64x136
static constexpr int G2_END   = G2_SC + 64 * G2_ST;    // halves
static constexpr int G2_SMEM  = G2_END * 2 + 128 * 4;  // 70144 B

__global__ __launch_bounds__(256, 3) void gemm2(
    const float* __restrict__ bup, float* __restrict__ out)
{
    extern __shared__ __half smC[];
    __half* shd = smC + G2_HD;
    __half* swu = smC + G2_WU;
    __half* ssc = smC + G2_SC;
    float*  sbup = (float*)(smC + G2_END);
    const int tid  = threadIdx.x;
    const int lane = tid & 31, warp = tid >> 5;
    const int nc = blockIdx.x;                 // col chunk (fastest)
    const int t0 = blockIdx.y * 64;            // token tile

    const int mw = warp >> 2, nw = warp & 3;
    const int gid = lane >> 2, tig = lane & 3;

    const int a_row = (lane & 7) + ((lane >> 3) & 1) * 8;
    const int a_kof = (lane >> 4) * 8;
    const int b_row = (lane & 7) + (lane >> 4) * 8;
    const int b_kof = ((lane >> 3) & 1) * 8;

    #pragma unroll
    for (int hk = 0; hk < 2; ++hk) {
        const int k0 = hk * 64;
        #pragma unroll
        for (int p = 0; p < 2; ++p) {           // hd: 64 x 64 halves
            const int idx = p * 256 + tid;
            const int row = idx >> 3, j = (idx & 7) * 8;
            cp16(shd + row * G2_ST + k0 + j, g_hd + (size_t)(t0 + row) * BN + k0 + j);
        }
        #pragma unroll
        for (int p = 0; p < 4; ++p) {           // Wu: 128 x 64 halves
            const int idx = p * 256 + tid;
            const int nn = idx >> 3, j = (idx & 7) * 8;
            cp16(swu + nn * G2_ST + k0 + j,
                 g_Wu + (size_t)(nc * 128 + nn) * BN + k0 + j);
        }
        cp_commit();
    }
    #pragma unroll
    for (int p = 0; p < 4; ++p) {               // shortcut: 64 x 128 halves
        const int idx = p * 256 + tid;
        const int row = idx >> 4, j = (idx & 15) * 8;
        cp16(ssc + row * G2_ST + j,
             g_sc + (size_t)(t0 + row) * DDIM + nc * 128 + j);
    }
    if (tid < 32) cp16(sbup + tid * 4, bup + nc * 128 + tid * 4);
    cp_commit();

    float acc[2][4][4];
    #pragma unroll
    for (int i = 0; i < 2; ++i)
        #pragma unroll
        for (int j = 0; j < 4; ++j)
            #pragma unroll
            for (int q = 0; q < 4; ++q) acc[i][j][q] = 0.f;

    #pragma unroll
    for (int hk = 0; hk < 2; ++hk) {
        if (hk == 0) cp_wait<2>(); else cp_wait<1>();
        __syncthreads();
        #pragma unroll
        for (int ks = 0; ks < 4; ++ks) {
            const int kb0 = hk * 64 + ks * 16;
            uint32_t a[2][4], bf[2][4];
            #pragma unroll
            for (int mt = 0; mt < 2; ++mt)
                ldsm4(a[mt], shd + (mw * 32 + mt * 16 + a_row) * G2_ST + kb0 + a_kof);
            #pragma unroll
            for (int nt2 = 0; nt2 < 2; ++nt2)
                ldsm4(bf[nt2], swu + (nw * 32 + nt2 * 16 + b_row) * G2_ST + kb0 + b_kof);
            #pragma unroll
            for (int mt = 0; mt < 2; ++mt)
                #pragma unroll
                for (int nt = 0; nt < 4; ++nt)
                    mma16(acc[mt][nt], a[mt], bf[nt >> 1] + (nt & 1) * 2);
        }
    }

    cp_wait<0>();
    __syncthreads();

    #pragma unroll
    for (int mt = 0; mt < 2; ++mt) {
        #pragma unroll
        for (int nt = 0; nt < 4; ++nt) {
            const int row  = mw * 32 + mt * 16 + gid;
            const int col  = nw * 32 + nt * 8 + 2 * tig;
            const int gcol = nc * 128 + col;
            const float b0 = sbup[col], b1 = sbup[col + 1];
            const size_t off  = (size_t)(t0 + row) * DDIM + gcol;
            const size_t off2 = off + (size_t)8 * DDIM;
            const float* c = acc[mt][nt];
            const float2 s0 = __half22float2(*(const __half2*)(ssc + row * G2_ST + col));
            const float2 s1 = __half22float2(*(const __half2*)(ssc + (row + 8) * G2_ST + col));
            float2 o0, o1;
            o0.x = c[0] + b0 + s0.x; o0.y = c[1] + b1 + s0.y;
            o1.x = c[2] + b0 + s1.x; o1.y = c[3] + b1 + s1.y;
            *(float2*)(out + off)  = o0;
            *(float2*)(out + off2) = o1;
        }
    }
}

// ------------------------------------------------------------------ launch
extern "C" void kernel_launch(void* const* d_in, const int* in_sizes, int n_in,
                              void* d_out, int out_size) {
    const float* x     = (const float*)d_in[0];
    const float* res   = (const float*)d_in[1];
    const float* gamma = (const float*)d_in[2];
    const float* beta  = (const float*)d_in[3];
    const float* Wd    = (const float*)d_in[4];
    const float* bd    = (const float*)d_in[5];
    const float* Wu    = (const float*)d_in[6];
    const float* bup   = (const float*)d_in[7];
    float* out = (float*)d_out;

    static bool attr_done = false;
    if (!attr_done) {
        cudaFuncSetAttribute(gemm1, cudaFuncAttributeMaxDynamicSharedMemorySize, G1_SMEM);
        cudaFuncSetAttribute(gemm2, cudaFuncAttributeMaxDynamicSharedMemorySize, G2_SMEM);
        attr_done = true;
    }

    convert_w<<<128, 256>>>(Wd, Wu, gamma);
    prep_s<<<128, 256>>>(Wd, gamma, beta, bd);
    resid_ln<<<4096, 256>>>(x, res);
    gemm1<<<512, 256, G1_SMEM>>>();
    gemm2<<<dim3(8, 512), 256, G2_SMEM>>>(bup, out);
}

// round 12
// speedup vs baseline: 1.4238x; 1.0340x over previous
#include <cuda_runtime.h>
#include <cuda_fp16.h>
#include <cstdint>

// LN folded into GEMM1; shortcut stored as half; TM=128 GEMM tiles.
// 1) convert_w: g_Wd = half(gamma ⊙ Wd), g_Wu = half(Wu)
// 2) prep_s   : s1 = Wd@gamma, s2 = Wd@beta + bd  (fp32, 128 each)
// 3) resid_ln : v = x+res^T -> g_sc (half); mu,rstd -> g_mu,g_rs
// 4) gemm1    : acc = v @ g_Wd^T; hd = relu(rstd*(acc - mu*s1) + s2) -> g_hd
//               (TM=128, 512 thr, 16 warps 4x4, single wave)
// 5) gemm2    : out = float(g_sc) + bup + hd @ g_Wu^T  (TM=128, grid (8,256))

#define NTOK 32768
#define DDIM 1024
#define BN   128

__device__ __align__(16) __half g_sc[(size_t)NTOK * DDIM];   // 64MB
__device__ __align__(16) __half g_hd[(size_t)NTOK * BN];     // 8MB
__device__ __align__(16) __half g_Wd[BN * DDIM];
__device__ __align__(16) __half g_Wu[DDIM * BN];
__device__ float g_mu[NTOK];
__device__ float g_rs[NTOK];
__device__ float g_s1[BN];
__device__ float g_s2[BN];

__device__ __forceinline__ void mma16(float* c, const uint32_t* a, const uint32_t* b) {
    asm volatile(
        "mma.sync.aligned.m16n8k16.row.col.f32.f16.f16.f32 "
        "{%0,%1,%2,%3}, {%4,%5,%6,%7}, {%8,%9}, {%0,%1,%2,%3};\n"
        : "+f"(c[0]), "+f"(c[1]), "+f"(c[2]), "+f"(c[3])
        : "r"(a[0]), "r"(a[1]), "r"(a[2]), "r"(a[3]), "r"(b[0]), "r"(b[1]));
}

__device__ __forceinline__ void ldsm4(uint32_t* r, const __half* p) {
    uint32_t a = (uint32_t)__cvta_generic_to_shared(p);
    asm volatile("ldmatrix.sync.aligned.m8n8.x4.shared.b16 {%0,%1,%2,%3}, [%4];\n"
                 : "=r"(r[0]), "=r"(r[1]), "=r"(r[2]), "=r"(r[3]) : "r"(a));
}

__device__ __forceinline__ void cp16(void* dst_sm, const void* src) {
    uint32_t a = (uint32_t)__cvta_generic_to_shared(dst_sm);
    asm volatile("cp.async.cg.shared.global [%0], [%1], 16;\n" :: "r"(a), "l"(src));
}
__device__ __forceinline__ void cp_commit() {
    asm volatile("cp.async.commit_group;\n");
}
template <int N>
__device__ __forceinline__ void cp_wait() {
    asm volatile("cp.async.wait_group %0;\n" :: "n"(N));
}

// ------------------------------------------------------------------ kernel 1
__global__ void convert_w(const float* __restrict__ Wd, const float* __restrict__ Wu,
                          const float* __restrict__ gamma) {
    const int i = (blockIdx.x * 256 + threadIdx.x) * 4; // 128 blocks
    float4 a = *(const float4*)(Wd + i);
    const int k = i & 1023;                             // col within Wd row
    const float4 g = *(const float4*)(gamma + k);
    a.x *= g.x; a.y *= g.y; a.z *= g.z; a.w *= g.w;
    const float4 b = *(const float4*)(Wu + i);
    __half2 a0 = __floats2half2_rn(a.x, a.y), a1 = __floats2half2_rn(a.z, a.w);
    __half2 b0 = __floats2half2_rn(b.x, b.y), b1 = __floats2half2_rn(b.z, b.w);
    uint2 ua, ub;
    ua.x = *(uint32_t*)&a0; ua.y = *(uint32_t*)&a1;
    ub.x = *(uint32_t*)&b0; ub.y = *(uint32_t*)&b1;
    *(uint2*)(g_Wd + i) = ua;
    *(uint2*)(g_Wu + i) = ub;
}

// ------------------------------------------------------------------ kernel 2
__global__ __launch_bounds__(256) void prep_s(
    const float* __restrict__ Wd, const float* __restrict__ gamma,
    const float* __restrict__ beta, const float* __restrict__ bd)
{
    __shared__ float r1[256], r2[256];
    const int j = blockIdx.x;                   // 128 blocks
    const int tid = threadIdx.x;
    const float* wr = Wd + (size_t)j * DDIM;
    float s1 = 0.f, s2 = 0.f;
    for (int k = tid; k < DDIM; k += 256) {
        const float w = wr[k];
        s1 += gamma[k] * w;
        s2 += beta[k] * w;
    }
    r1[tid] = s1; r2[tid] = s2;
    __syncthreads();
    for (int o = 128; o > 0; o >>= 1) {
        if (tid < o) { r1[tid] += r1[tid + o]; r2[tid] += r2[tid + o]; }
        __syncthreads();
    }
    if (tid == 0) { g_s1[j] = r1[0]; g_s2[j] = r2[0] + bd[j]; }
}

// ------------------------------------------------------------------ kernel 3
__global__ __launch_bounds__(256) void resid_ln(
    const float* __restrict__ x, const float* __restrict__ res)
{
    const int warp = threadIdx.x >> 5, lane = threadIdx.x & 31;
    const int n = blockIdx.x * 8 + warp;           // 4096 blocks
    const int s = n >> 3, b = n & 7;
    const float4* xr = (const float4*)(x + (size_t)n * DDIM);
    const float4* rr = (const float4*)(res + ((size_t)b * 4096 + s) * DDIM);
    uint2* hrow = (uint2*)(g_sc + (size_t)n * DDIM);

    float sum = 0.f, sq = 0.f;
    #pragma unroll
    for (int i = 0; i < 8; ++i) {
        const int k = i * 32 + lane;
        const float4 a = xr[k], r = rr[k];
        float4 t;
        t.x = a.x + r.x; t.y = a.y + r.y; t.z = a.z + r.z; t.w = a.w + r.w;
        sum += t.x + t.y + t.z + t.w;
        sq  += t.x * t.x + t.y * t.y + t.z * t.z + t.w * t.w;
        __half2 h0 = __floats2half2_rn(t.x, t.y);
        __half2 h1 = __floats2half2_rn(t.z, t.w);
        uint2 u;
        u.x = *(uint32_t*)&h0;
        u.y = *(uint32_t*)&h1;
        hrow[k] = u;
    }
    #pragma unroll
    for (int o = 16; o > 0; o >>= 1) {
        sum += __shfl_xor_sync(0xffffffffu, sum, o);
        sq  += __shfl_xor_sync(0xffffffffu, sq, o);
    }
    if (lane == 0) {
        const float mu  = sum * (1.f / 1024.f);
        const float var = sq * (1.f / 1024.f) - mu * mu;
        g_mu[n] = mu;
        g_rs[n] = rsqrtf(var + 1e-5f);
    }
}

// ------------------------------------------------------------------ kernel 4
// CTA: 128 tokens x 128(BN), 512 threads (16 warps = 4m x 4n, warp tile 32x32).
// K chunks of 64 halves, single-sync 2-stage pipeline. 256 CTAs, single wave.
static constexpr int OFF1_MU  = 0;                       // 128 f
static constexpr int OFF1_RS  = 512;
static constexpr int OFF1_S1  = 1024;
static constexpr int OFF1_S2  = 1536;
static constexpr int OFF1_T   = 2048;
static constexpr int G1_AST   = 72;
static constexpr int G1_STG   = (128 + 128) * G1_AST;    // halves
static constexpr int G1_SMEM  = OFF1_T + 2 * G1_STG * 2; // 75776 B

__global__ __launch_bounds__(512, 2) void gemm1()
{
    extern __shared__ char smem1[];
    float*  smu = (float*)(smem1 + OFF1_MU);
    float*  srs = (float*)(smem1 + OFF1_RS);
    float*  ss1 = (float*)(smem1 + OFF1_S1);
    float*  ss2 = (float*)(smem1 + OFF1_S2);
    __half* smB = (__half*)(smem1 + OFF1_T);
    const int tid  = threadIdx.x;
    const int lane = tid & 31, warp = tid >> 5;
    const int t0   = (int)(gridDim.x - 1 - blockIdx.x) * 128;

    const int mw = warp >> 2, nw = warp & 3;          // 4 x 4
    const int gid = lane >> 2, tig = lane & 3;
    const int a_row = (lane & 7) + ((lane >> 3) & 1) * 8;
    const int a_kof = (lane >> 4) * 8;
    const int b_row = (lane & 7) + (lane >> 4) * 8;
    const int b_kof = ((lane >> 3) & 1) * 8;

    if (tid < 128)       { smu[tid] = g_mu[t0 + tid]; srs[tid] = g_rs[t0 + tid]; }
    else if (tid < 256)  {
        const int j = tid - 128;
        ss1[j] = g_s1[j];
        ss2[j] = g_s2[j];
    }

    auto issue = [&](int st, int kc) {
        __half* s = smB + st * G1_STG;
        const int kg0 = kc * 64;
        #pragma unroll
        for (int p = 0; p < 2; ++p) {           // A: 128 x 64 halves from g_sc
            const int idx = p * 512 + tid;
            const int row = idx >> 3, j = (idx & 7) * 8;
            cp16(s + row * G1_AST + j, g_sc + (size_t)(t0 + row) * DDIM + kg0 + j);
        }
        #pragma unroll
        for (int p = 0; p < 2; ++p) {           // B: 128 x 64 halves
            const int idx = p * 512 + tid;
            const int nn = idx >> 3, j = (idx & 7) * 8;
            cp16(s + 128 * G1_AST + nn * G1_AST + j, g_Wd + (size_t)nn * DDIM + kg0 + j);
        }
        cp_commit();
    };

    float acc[2][4][4];
    #pragma unroll
    for (int i = 0; i < 2; ++i)
        #pragma unroll
        for (int j = 0; j < 4; ++j)
            #pragma unroll
            for (int q = 0; q < 4; ++q) acc[i][j][q] = 0.f;

    issue(0, 0);

    #pragma unroll 1
    for (int kc = 0; kc < 16; ++kc) {
        cp_wait<0>();
        __syncthreads();
        if (kc + 1 < 16) issue((kc + 1) & 1, kc + 1);   // overlaps this MMA chunk
        const __half* sa = smB + (kc & 1) * G1_STG;
        const __half* sb = sa + 128 * G1_AST;
        #pragma unroll
        for (int ks = 0; ks < 4; ++ks) {
            const int kb0 = ks * 16;
            uint32_t a[2][4], bf[2][4];
            #pragma unroll
            for (int mt = 0; mt < 2; ++mt)
                ldsm4(a[mt], sa + (mw * 32 + mt * 16 + a_row) * G1_AST + kb0 + a_kof);
            #pragma unroll
            for (int nt2 = 0; nt2 < 2; ++nt2)
                ldsm4(bf[nt2], sb + (nw * 32 + nt2 * 16 + b_row) * G1_AST + kb0 + b_kof);
            #pragma unroll
            for (int mt = 0; mt < 2; ++mt)
                #pragma unroll
                for (int nt = 0; nt < 4; ++nt)
                    mma16(acc[mt][nt], a[mt], bf[nt >> 1] + (nt & 1) * 2);
        }
    }

    // epilogue: hd = relu(rstd*(acc - mu*s1) + s2) -> g_hd
    #pragma unroll
    for (int mt = 0; mt < 2; ++mt) {
        #pragma unroll
        for (int nt = 0; nt < 4; ++nt) {
            const int row = mw * 32 + mt * 16 + gid;
            const int col = nw * 32 + nt * 8 + 2 * tig;
            const float mu0 = smu[row],     rs0 = srs[row];
            const float mu1 = smu[row + 8], rs1 = srs[row + 8];
            const float s10 = ss1[col], s11 = ss1[col + 1];
            const float s20 = ss2[col], s21 = ss2[col + 1];
            const float* c = acc[mt][nt];
            const size_t o = (size_t)(t0 + row) * BN + col;
            __half2 h0 = __floats2half2_rn(
                fmaxf(rs0 * (c[0] - mu0 * s10) + s20, 0.f),
                fmaxf(rs0 * (c[1] - mu0 * s11) + s21, 0.f));
            __half2 h1 = __floats2half2_rn(
                fmaxf(rs1 * (c[2] - mu1 * s10) + s20, 0.f),
                fmaxf(rs1 * (c[3] - mu1 * s11) + s21, 0.f));
            *(uint32_t*)(g_hd + o)          = *(uint32_t*)&h0;
            *(uint32_t*)(g_hd + o + 8 * BN) = *(uint32_t*)&h1;
        }
    }
}

// ------------------------------------------------------------------ kernel 5
// CTA: 128 tokens x 128 out-cols, 512 threads (16 warps 4x4). Grid (8, 256).
static constexpr int G2_ST    = 136;                   // halves
static constexpr int G2_HD    = 0;                     // shd 128x136
static constexpr int G2_WU    = 128 * G2_ST;           // swu 128x136
static constexpr int G2_SC    = G2_WU + 128 * G2_ST;   // ssc 128x136
static constexpr int G2_END   = G2_SC + 128 * G2_ST;   // halves
static constexpr int G2_SMEM  = G2_END * 2 + 128 * 4;  // 104960 B

__global__ __launch_bounds__(512, 2) void gemm2(
    const float* __restrict__ bup, float* __restrict__ out)
{
    extern __shared__ __half smC[];
    __half* shd = smC + G2_HD;
    __half* swu = smC + G2_WU;
    __half* ssc = smC + G2_SC;
    float*  sbup = (float*)(smC + G2_END);
    const int tid  = threadIdx.x;
    const int lane = tid & 31, warp = tid >> 5;
    const int nc = blockIdx.x;                 // col chunk (fastest)
    const int t0 = blockIdx.y * 128;           // token tile

    const int mw = warp >> 2, nw = warp & 3;   // 4 x 4
    const int gid = lane >> 2, tig = lane & 3;

    const int a_row = (lane & 7) + ((lane >> 3) & 1) * 8;
    const int a_kof = (lane >> 4) * 8;
    const int b_row = (lane & 7) + (lane >> 4) * 8;
    const int b_kof = ((lane >> 3) & 1) * 8;

    #pragma unroll
    for (int hk = 0; hk < 2; ++hk) {
        const int k0 = hk * 64;
        #pragma unroll
        for (int p = 0; p < 2; ++p) {           // hd: 128 x 64 halves
            const int idx = p * 512 + tid;
            const int row = idx >> 3, j = (idx & 7) * 8;
            cp16(shd + row * G2_ST + k0 + j, g_hd + (size_t)(t0 + row) * BN + k0 + j);
        }
        #pragma unroll
        for (int p = 0; p < 2; ++p) {           // Wu: 128 x 64 halves
            const int idx = p * 512 + tid;
            const int nn = idx >> 3, j = (idx & 7) * 8;
            cp16(swu + nn * G2_ST + k0 + j,
                 g_Wu + (size_t)(nc * 128 + nn) * BN + k0 + j);
        }
        cp_commit();
    }
    #pragma unroll
    for (int p = 0; p < 4; ++p) {               // shortcut: 128 x 128 halves
        const int idx = p * 512 + tid;
        const int row = idx >> 4, j = (idx & 15) * 8;
        cp16(ssc + row * G2_ST + j,
             g_sc + (size_t)(t0 + row) * DDIM + nc * 128 + j);
    }
    if (tid < 32) cp16(sbup + tid * 4, bup + nc * 128 + tid * 4);
    cp_commit();

    float acc[2][4][4];
    #pragma unroll
    for (int i = 0; i < 2; ++i)
        #pragma unroll
        for (int j = 0; j < 4; ++j)
            #pragma unroll
            for (int q = 0; q < 4; ++q) acc[i][j][q] = 0.f;

    #pragma unroll
    for (int hk = 0; hk < 2; ++hk) {
        if (hk == 0) cp_wait<2>(); else cp_wait<1>();
        __syncthreads();
        #pragma unroll
        for (int ks = 0; ks < 4; ++ks) {
            const int kb0 = hk * 64 + ks * 16;
            uint32_t a[2][4], bf[2][4];
            #pragma unroll
            for (int mt = 0; mt < 2; ++mt)
                ldsm4(a[mt], shd + (mw * 32 + mt * 16 + a_row) * G2_ST + kb0 + a_kof);
            #pragma unroll
            for (int nt2 = 0; nt2 < 2; ++nt2)
                ldsm4(bf[nt2], swu + (nw * 32 + nt2 * 16 + b_row) * G2_ST + kb0 + b_kof);
            #pragma unroll
            for (int mt = 0; mt < 2; ++mt)
                #pragma unroll
                for (int nt = 0; nt < 4; ++nt)
                    mma16(acc[mt][nt], a[mt], bf[nt >> 1] + (nt & 1) * 2);
        }
    }

    cp_wait<0>();
    __syncthreads();

    #pragma unroll
    for (int mt = 0; mt < 2; ++mt) {
        #pragma unroll
        for (int nt = 0; nt < 4; ++nt) {
            const int row  = mw * 32 + mt * 16 + gid;
            const int col  = nw * 32 + nt * 8 + 2 * tig;
            const int gcol = nc * 128 + col;
            const float b0 = sbup[col], b1 = sbup[col + 1];
            const size_t off  = (size_t)(t0 + row) * DDIM + gcol;
            const size_t off2 = off + (size_t)8 * DDIM;
            const float* c = acc[mt][nt];
            const float2 s0 = __half22float2(*(const __half2*)(ssc + row * G2_ST + col));
            const float2 s1 = __half22float2(*(const __half2*)(ssc + (row + 8) * G2_ST + col));
            float2 o0, o1;
            o0.x = c[0] + b0 + s0.x; o0.y = c[1] + b1 + s0.y;
            o1.x = c[2] + b0 + s1.x; o1.y = c[3] + b1 + s1.y;
            *(float2*)(out + off)  = o0;
            *(float2*)(out + off2) = o1;
        }
    }
}

// ------------------------------------------------------------------ launch
extern "C" void kernel_launch(void* const* d_in, const int* in_sizes, int n_in,
                              void* d_out, int out_size) {
    const float* x     = (const float*)d_in[0];
    const float* res   = (const float*)d_in[1];
    const float* gamma = (const float*)d_in[2];
    const float* beta  = (const float*)d_in[3];
    const float* Wd    = (const float*)d_in[4];
    const float* bd    = (const float*)d_in[5];
    const float* Wu    = (const float*)d_in[6];
    const float* bup   = (const float*)d_in[7];
    float* out = (float*)d_out;

    static bool attr_done = false;
    if (!attr_done) {
        cudaFuncSetAttribute(gemm1, cudaFuncAttributeMaxDynamicSharedMemorySize, G1_SMEM);
        cudaFuncSetAttribute(gemm2, cudaFuncAttributeMaxDynamicSharedMemorySize, G2_SMEM);
        attr_done = true;
    }

    convert_w<<<128, 256>>>(Wd, Wu, gamma);
    prep_s<<<128, 256>>>(Wd, gamma, beta, bd);
    resid_ln<<<4096, 256>>>(x, res);
    gemm1<<<256, 512, G1_SMEM>>>();
    gemm2<<<dim3(8, 256), 512, G2_SMEM>>>(bup, out);
}